// round 10
// baseline (speedup 1.0000x reference)
#include <cuda_runtime.h>
#include <cuda_fp16.h>
#include <math.h>
#include <stdint.h>

// ---------------- scratch (no allocations allowed) ----------------
__device__ __half g_qkv_h[113246208UL];  // 36864 x 3072 (GEMM1 out, fp16)
__device__ __half g_mid_h[37748736UL];   // 36864 x 1024 (attn out, fp16)
__device__ __half g_x_h[37748736UL];     // x converted to fp16
__device__ __half g_wt_h[4194304UL];     // Wt_qkv [3072,1024] + Wt_out [1024,1024]
__device__ float2 g_rope[1024];          // cos/sin(t * inv_freq[j])

__device__ __forceinline__ float sigma_fn(float x) {
    return x > 0.f ? x + 1.f : __expf(x);
}
__device__ __forceinline__ void cp_async16(uint32_t saddr, const void* gptr) {
    asm volatile("cp.async.cg.shared.global [%0], [%1], 16;\n" :: "r"(saddr), "l"(gptr));
}
__device__ __forceinline__ uint32_t smem_u32(const void* p) {
    uint32_t a;
    asm("{ .reg .u64 t; cvta.to.shared.u64 t, %1; cvt.u32.u64 %0, t; }" : "=r"(a) : "l"(p));
    return a;
}
#define LDSM4(r0, r1, r2, r3, addr) \
    asm volatile("ldmatrix.sync.aligned.m8n8.x4.shared.b16 {%0,%1,%2,%3}, [%4];" \
                 : "=r"(r0), "=r"(r1), "=r"(r2), "=r"(r3) : "r"(addr))
#define MMA16816(d0, d1, d2, d3, a0, a1, a2, a3, b0, b1) \
    asm volatile("mma.sync.aligned.m16n8k16.row.col.f32.f16.f16.f32 " \
                 "{%0,%1,%2,%3}, {%4,%5,%6,%7}, {%8,%9}, {%0,%1,%2,%3};\n" \
                 : "+f"(d0), "+f"(d1), "+f"(d2), "+f"(d3) \
                 : "r"(a0), "r"(a1), "r"(a2), "r"(a3), "r"(b0), "r"(b1))

// swizzled byte offset inside a [rows][64-half] fp16 tile (128B rows, SW128)
__device__ __forceinline__ uint32_t swa(uint32_t row, uint32_t col) {
    return row * 128u + ((((col >> 3) ^ (row & 7)) << 4) | ((col & 7) << 1));
}

// ================= fp16 mma.sync GEMM, ldmatrix + SW128 (round 9, proven) =====
#define A_ST 16384
#define STG  32768
#define NST  3
#define GEMM_SMEM (NST * STG)

template<bool HALF_OUT>
__global__ __launch_bounds__(256, 2)
void gemm_h(int N, int K,
            const __half* __restrict__ A,
            const __half* __restrict__ Bt,
            void* __restrict__ Cout,
            const float* __restrict__ bias)
{
    extern __shared__ char smem[];
    const uint32_t sbase = smem_u32(smem);
    const int tid  = threadIdx.x;
    const int warp = tid >> 5;
    const int lane = tid & 31;
    const int g    = lane >> 2;
    const int t4   = lane & 3;
    const int wm0  = (warp & 1) * 64;
    const int wn0  = (warp >> 1) * 32;

    const size_t m0 = (size_t)blockIdx.y * 128;
    const size_t n0 = (size_t)blockIdx.x * 128;

    const int lrow = tid >> 3;
    const int lc8  = tid & 7;
    const __half* gA = A  + (m0 + lrow) * K + lc8 * 8;
    const __half* gB = Bt + (n0 + lrow) * K + lc8 * 8;
    const uint32_t stA = lrow * 128 + ((lc8 ^ (lrow & 7)) << 4);
    const uint32_t stB = stA + A_ST;

    uint32_t abase[4], bbase[2];
    {
        const uint32_t sw = (((lane >> 4) ^ (lane & 7)) << 4);
        #pragma unroll
        for (int mt = 0; mt < 4; mt++)
            abase[mt] = (wm0 + mt * 16 + (lane & 15)) * 128 + sw;
        #pragma unroll
        for (int p = 0; p < 2; p++)
            bbase[p] = A_ST + (wn0 + p * 16 + (lane & 15)) * 128 + sw;
    }

    const int nch = K >> 6;

    float acc[4][4][4];
    #pragma unroll
    for (int i = 0; i < 4; i++)
        #pragma unroll
        for (int j = 0; j < 4; j++)
            #pragma unroll
            for (int r = 0; r < 4; r++) acc[i][j][r] = 0.f;

    #pragma unroll
    for (int s = 0; s < 2; s++) {
        #pragma unroll
        for (int u = 0; u < 4; u++) {
            cp_async16(sbase + stA + s * STG + u * 4096, gA + (size_t)u * 32 * K + s * 64);
            cp_async16(sbase + stB + s * STG + u * 4096, gB + (size_t)u * 32 * K + s * 64);
        }
        asm volatile("cp.async.commit_group;\n");
    }

    for (int c = 0; c < nch; c++) {
        asm volatile("cp.async.wait_group 1;\n");
        __syncthreads();

        const int nc = c + 2;
        if (nc < nch) {
            const int ns = nc % 3;
            #pragma unroll
            for (int u = 0; u < 4; u++) {
                cp_async16(sbase + stA + ns * STG + u * 4096, gA + (size_t)u * 32 * K + nc * 64);
                cp_async16(sbase + stB + ns * STG + u * 4096, gB + (size_t)u * 32 * K + nc * 64);
            }
        }
        asm volatile("cp.async.commit_group;\n");

        const uint32_t so = sbase + (c % 3) * STG;

        #pragma unroll
        for (int ks = 0; ks < 4; ks++) {
            const uint32_t kx = (uint32_t)ks << 5;
            uint32_t a[4][4], b[4][2];
            #pragma unroll
            for (int mt = 0; mt < 4; mt++)
                LDSM4(a[mt][0], a[mt][1], a[mt][2], a[mt][3], so + (abase[mt] ^ kx));
            #pragma unroll
            for (int p = 0; p < 2; p++)
                LDSM4(b[2 * p][0], b[2 * p + 1][0], b[2 * p][1], b[2 * p + 1][1],
                      so + (bbase[p] ^ kx));
            #pragma unroll
            for (int mt = 0; mt < 4; mt++)
                #pragma unroll
                for (int nt = 0; nt < 4; nt++)
                    MMA16816(acc[mt][nt][0], acc[mt][nt][1], acc[mt][nt][2], acc[mt][nt][3],
                             a[mt][0], a[mt][1], a[mt][2], a[mt][3], b[nt][0], b[nt][1]);
        }
    }

    #pragma unroll
    for (int mt = 0; mt < 4; mt++) {
        const size_t r0 = m0 + wm0 + mt * 16 + g;
        const size_t r1 = r0 + 8;
        #pragma unroll
        for (int nt = 0; nt < 4; nt++) {
            const int col = (int)n0 + wn0 + nt * 8 + t4 * 2;
            if (HALF_OUT) {
                __half* C = (__half*)Cout;
                *(__half2*)(C + r0 * N + col) = __floats2half2_rn(acc[mt][nt][0], acc[mt][nt][1]);
                *(__half2*)(C + r1 * N + col) = __floats2half2_rn(acc[mt][nt][2], acc[mt][nt][3]);
            } else {
                float* C = (float*)Cout;
                float b0 = bias ? bias[col] : 0.f;
                float b1 = bias ? bias[col + 1] : 0.f;
                *(float2*)(C + r0 * N + col) = make_float2(acc[mt][nt][0] + b0, acc[mt][nt][1] + b1);
                *(float2*)(C + r1 * N + col) = make_float2(acc[mt][nt][2] + b0, acc[mt][nt][3] + b1);
            }
        }
    }
}

// ---------------- preprocessing (unchanged) ----------------
__global__ __launch_bounds__(256)
void convert_x_kernel(const float4* __restrict__ in, uint4* __restrict__ out, int n8) {
    int i = blockIdx.x * 256 + threadIdx.x;
    if (i >= n8) return;
    float4 f0 = in[2 * i], f1 = in[2 * i + 1];
    __half2 h[4];
    h[0] = __floats2half2_rn(f0.x, f0.y);
    h[1] = __floats2half2_rn(f0.z, f0.w);
    h[2] = __floats2half2_rn(f1.x, f1.y);
    h[3] = __floats2half2_rn(f1.z, f1.w);
    out[i] = *(const uint4*)h;
}

__global__ __launch_bounds__(256)
void transpose_half_kernel(const float* __restrict__ in, __half* __restrict__ out,
                           int Kk, int Nn) {
    __shared__ float t[32][33];
    const int n0 = blockIdx.x * 32;
    const int k0 = blockIdx.y * 32;
    const int tx = threadIdx.x & 31;
    const int ty = threadIdx.x >> 5;
    #pragma unroll
    for (int r = 0; r < 4; r++) {
        int kr = ty + r * 8;
        t[kr][tx] = in[(size_t)(k0 + kr) * Nn + n0 + tx];
    }
    __syncthreads();
    if (threadIdx.x < 64) {
        const int nl = threadIdx.x >> 1;
        const int kg = threadIdx.x & 1;
        __half h[16];
        #pragma unroll
        for (int o = 0; o < 16; o++)
            h[o] = __float2half_rn(t[kg * 16 + o][nl]);
        uint4* o4 = (uint4*)(out + (size_t)(n0 + nl) * Kk + k0 + kg * 16);
        o4[0] = ((const uint4*)h)[0];
        o4[1] = ((const uint4*)h)[1];
    }
}

__global__ void rope_table_kernel(const float* __restrict__ inv_freq,
                                  float2* __restrict__ tab) {
    int t = threadIdx.x >> 5, j = threadIdx.x & 31;
    float sn, cs;
    sincosf((float)t * inv_freq[j], &sn, &cs);
    tab[t * 32 + j] = make_float2(cs, sn);
}

// ---------------- fused attention: out-phase on tensor cores ----------------
#define TSEQ 32
#define DHD 64
#define P 68

struct AttnSmem {
    __half sch[32 * 64];    // softmax weights, K-padded (cols 32..63 = 0), swizzled
    __half sqh[32 * 64];    // sigma(q_rot), swizzled
    __half vTh[64 * 64];    // v^T [d][s], cols 32..63 = 0, swizzled
    __half memT[64 * 64];   // mem^T [v][k], swizzled
    float qs[TSEQ][P];
    float ks[TSEQ][P];
    float vs[TSEQ][P];      // v; reused as output staging in the final phase
    float ms[DHD][P];
    float sc[TSEQ][33];
    float skk[8][P];
    float2 rope[TSEQ][32];
    float zs[DHD];
    float denom[TSEQ];
};

__global__ __launch_bounds__(256)
void attn_kernel(const __half* __restrict__ qkv,
                 const float* __restrict__ mem,
                 const float* __restrict__ zin,
                 const float* __restrict__ mem_beta,
                 const float2* __restrict__ rope_tab,
                 __half* __restrict__ out_mid,
                 float* __restrict__ new_mem,
                 float* __restrict__ new_z)
{
    extern __shared__ __align__(128) char smem_raw[];
    AttnSmem& S = *(AttnSmem*)smem_raw;
    char* schp = (char*)S.sch;
    char* sqhp = (char*)S.sqh;
    char* vthp = (char*)S.vTh;
    char* memp = (char*)S.memT;

    const int bh   = blockIdx.x;
    const int s    = bh >> 4;
    const int head = bh & 15;
    const int b    = s / 576;
    const int rem  = s - b * 576;
    const int tid  = threadIdx.x;
    const int warp = tid >> 5;
    const int lane = tid & 31;
    const int row_base = b * 18432 + rem;
    const size_t mbase = (size_t)bh * (DHD * DHD);

    const float g = 1.f / (1.f + __expf(-mem_beta[head]));
    const float ig = 1.f - g;

    // ---- P1: load qkv (half2), mem, z, rope table ----
    for (int e = tid; e < 1024; e += 256) {
        int t = e >> 5, d2 = (e & 31) * 2;
        size_t base = (size_t)(row_base + t * 576) * 3072 + head * 64 + d2;
        float2 q = __half22float2(*(const __half2*)(qkv + base));
        float2 k = __half22float2(*(const __half2*)(qkv + base + 1024));
        float2 v = __half22float2(*(const __half2*)(qkv + base + 2048));
        S.qs[t][d2] = q.x; S.qs[t][d2 + 1] = q.y;
        S.ks[t][d2] = k.x; S.ks[t][d2 + 1] = k.y;
        S.vs[t][d2] = v.x; S.vs[t][d2 + 1] = v.y;
        ((float2*)S.rope)[e] = rope_tab[e];
    }
    for (int e = tid; e < 4096; e += 256)
        S.ms[e >> 6][e & 63] = mem[mbase + e];
    if (tid < DHD) S.zs[tid] = zin[(size_t)bh * DHD + tid];
    __syncthreads();

    // ---- P2a: skk, new_z, vTh (fp16 transposed+padded), memT (fp16 transposed) ----
    for (int e = tid; e < 8 * DHD; e += 256) {
        int t = e >> 6, i = e & 63;
        S.skk[t][i] = sigma_fn(sigma_fn(S.ks[t][i]));
    }
    if (tid < DHD) {
        float acc = S.zs[tid];
        #pragma unroll
        for (int t = 0; t < TSEQ; t++) acc += sigma_fn(S.ks[t][tid]);
        new_z[(size_t)bh * DHD + tid] = acc;
    }
    for (int e = tid; e < 2048; e += 256) {
        int d = e >> 5, s2 = (e & 31) * 2;
        __half2 h = (s2 < 32) ? __floats2half2_rn(S.vs[s2][d], S.vs[s2 + 1][d])
                              : __floats2half2_rn(0.f, 0.f);
        *(__half2*)(vthp + swa(d, s2)) = h;
    }
    for (int e = tid; e < 2048; e += 256) {
        int vc = e >> 5, k2 = (e & 31) * 2;
        __half2 h = __floats2half2_rn(S.ms[k2][vc], S.ms[k2 + 1][vc]);
        *(__half2*)(memp + swa(vc, k2)) = h;
    }
    __syncthreads();

    // ---- P2b: new_mem + rotary ----
    for (int e = tid; e < 4096; e += 256) {
        int i = e >> 6, j = e & 63;
        float acc = S.ms[i][j];
        #pragma unroll
        for (int t = 0; t < 8; t++) acc += S.skk[t][i] * S.vs[t][j];
        new_mem[mbase + e] = acc;
    }
    for (int e = tid; e < 1024; e += 256) {
        int t = e >> 5, j = e & 31;
        float2 cssn = S.rope[t][j];
        float q0 = S.qs[t][2 * j], q1 = S.qs[t][2 * j + 1];
        S.qs[t][2 * j]     = q0 * cssn.x - q1 * cssn.y;
        S.qs[t][2 * j + 1] = q1 * cssn.x + q0 * cssn.y;
        float k0 = S.ks[t][2 * j], k1 = S.ks[t][2 * j + 1];
        S.ks[t][2 * j]     = k0 * cssn.x - k1 * cssn.y;
        S.ks[t][2 * j + 1] = k1 * cssn.x + k0 * cssn.y;
    }
    __syncthreads();

    // ---- P3: scores (f32, 2x2 reg tile) + sqh (fp16 swizzled) + denom (f32) ----
    {
        const int tr = tid >> 4;
        const int tc = tid & 15;
        float a00 = 0.f, a01 = 0.f, a10 = 0.f, a11 = 0.f;
        #pragma unroll
        for (int d = 0; d < DHD; d += 4) {
            float4 q0 = *(const float4*)&S.qs[tr][d];
            float4 q1 = *(const float4*)&S.qs[tr + 16][d];
            float4 k0 = *(const float4*)&S.ks[tc][d];
            float4 k1 = *(const float4*)&S.ks[tc + 16][d];
            a00 += q0.x * k0.x + q0.y * k0.y + q0.z * k0.z + q0.w * k0.w;
            a01 += q0.x * k1.x + q0.y * k1.y + q0.z * k1.z + q0.w * k1.w;
            a10 += q1.x * k0.x + q1.y * k0.y + q1.z * k0.z + q1.w * k0.w;
            a11 += q1.x * k1.x + q1.y * k1.y + q1.z * k1.z + q1.w * k1.w;
        }
        S.sc[tr][tc]           = a00 * 0.125f;
        S.sc[tr][tc + 16]      = a01 * 0.125f;
        S.sc[tr + 16][tc]      = a10 * 0.125f;
        S.sc[tr + 16][tc + 16] = a11 * 0.125f;
    }
    for (int e = tid; e < 1024; e += 256) {
        int t = e >> 5, c2 = (e & 31) * 2;
        __half2 h = __floats2half2_rn(sigma_fn(S.qs[t][c2]), sigma_fn(S.qs[t][c2 + 1]));
        *(__half2*)(sqhp + swa(t, c2)) = h;
    }
    if (tid < TSEQ) {
        float acc = 0.f;
        #pragma unroll
        for (int kx = 0; kx < DHD; kx++) acc += sigma_fn(S.qs[tid][kx]) * S.zs[kx];
        S.denom[tid] = acc;
    }
    __syncthreads();

    // ---- P4: warp-parallel softmax ----
    #pragma unroll
    for (int r = 0; r < 4; r++) {
        int t = warp * 4 + r;
        float v = (lane <= t) ? S.sc[t][lane] : -1e30f;
        float m = v;
        #pragma unroll
        for (int o = 16; o > 0; o >>= 1) m = fmaxf(m, __shfl_xor_sync(0xFFFFFFFFu, m, o));
        float ex = (lane <= t) ? __expf(v - m) : 0.f;
        float ssum = ex;
        #pragma unroll
        for (int o = 16; o > 0; o >>= 1) ssum += __shfl_xor_sync(0xFFFFFFFFu, ssum, o);
        S.sc[t][lane] = ex / ssum;
    }
    __syncthreads();

    // ---- P5: sch = softmax weights fp16, K-padded, swizzled ----
    for (int e = tid; e < 1024; e += 256) {
        int t = e >> 5, s2 = (e & 31) * 2;
        __half2 h = (s2 < 32) ? __floats2half2_rn(S.sc[t][s2], S.sc[t][s2 + 1])
                              : __floats2half2_rn(0.f, 0.f);
        *(__half2*)(schp + swa(t, s2)) = h;
    }
    __syncthreads();

    // ---- P6: out = g*(sqh@memT)/denom + (1-g)*(sch@vTh) via HMMA, stage to vs ----
    {
        const int mt  = warp & 1;
        const int ntp = warp >> 1;       // 0..3, 16-col groups
        const int lg  = lane >> 2;
        const int t4  = lane & 3;
        const uint32_t sw = (((lane >> 4) ^ (lane & 7)) << 4);
        const uint32_t arow = (mt * 16 + (lane & 15)) * 128 + sw;
        const uint32_t brow = (ntp * 16 + (lane & 15)) * 128 + sw;
        const uint32_t schb = smem_u32(S.sch) + arow;
        const uint32_t sqhb = smem_u32(S.sqh) + arow;
        const uint32_t vthb = smem_u32(S.vTh) + brow;
        const uint32_t memb = smem_u32(S.memT) + brow;

        float accA[2][4], accR[2][4];
        #pragma unroll
        for (int nt = 0; nt < 2; nt++)
            #pragma unroll
            for (int r = 0; r < 4; r++) { accA[nt][r] = 0.f; accR[nt][r] = 0.f; }

        #pragma unroll
        for (int ks = 0; ks < 4; ks++) {
            const uint32_t kx = (uint32_t)ks << 5;
            uint32_t as0, as1, as2, as3, aq0, aq1, aq2, aq3;
            uint32_t bv[2][2], bm[2][2];
            LDSM4(as0, as1, as2, as3, schb ^ kx);
            LDSM4(aq0, aq1, aq2, aq3, sqhb ^ kx);
            LDSM4(bv[0][0], bv[1][0], bv[0][1], bv[1][1], vthb ^ kx);
            LDSM4(bm[0][0], bm[1][0], bm[0][1], bm[1][1], memb ^ kx);
            #pragma unroll
            for (int nt = 0; nt < 2; nt++) {
                MMA16816(accA[nt][0], accA[nt][1], accA[nt][2], accA[nt][3],
                         as0, as1, as2, as3, bv[nt][0], bv[nt][1]);
                MMA16816(accR[nt][0], accR[nt][1], accR[nt][2], accR[nt][3],
                         aq0, aq1, aq2, aq3, bm[nt][0], bm[nt][1]);
            }
        }

        const int r0 = mt * 16 + lg;
        const int r1 = r0 + 8;
        const float gi0 = g / S.denom[r0];
        const float gi1 = g / S.denom[r1];
        #pragma unroll
        for (int nt = 0; nt < 2; nt++) {
            const int col = ntp * 16 + nt * 8 + t4 * 2;
            S.vs[r0][col]     = gi0 * accR[nt][0] + ig * accA[nt][0];
            S.vs[r0][col + 1] = gi0 * accR[nt][1] + ig * accA[nt][1];
            S.vs[r1][col]     = gi1 * accR[nt][2] + ig * accA[nt][2];
            S.vs[r1][col + 1] = gi1 * accR[nt][3] + ig * accA[nt][3];
        }
    }
    __syncthreads();

    // ---- P7: coalesced fp16 writeback ----
    for (int e = tid; e < 1024; e += 256) {
        int t = e >> 5, dd = (e & 31) * 2;
        __half2 h = __floats2half2_rn(S.vs[t][dd], S.vs[t][dd + 1]);
        *(__half2*)(out_mid + (size_t)(row_base + t * 576) * 1024 + head * 64 + dd) = h;
    }
}

// ---------------- launch ----------------
extern "C" void kernel_launch(void* const* d_in, const int* in_sizes, int n_in,
                              void* d_out, int out_size) {
    const float* x        = (const float*)d_in[0];
    const float* mem      = (const float*)d_in[1];
    const float* z        = (const float*)d_in[2];
    const float* W_qkv    = (const float*)d_in[3];
    const float* W_out    = (const float*)d_in[4];
    const float* b_out    = (const float*)d_in[5];
    const float* mem_beta = (const float*)d_in[6];
    const float* inv_freq = (const float*)d_in[7];

    float* x_out = (float*)d_out;
    float* nmem  = x_out + 37748736UL;
    float* nz    = x_out + 113246208UL;

    __half *qkv = nullptr, *mid = nullptr, *xh = nullptr, *wt = nullptr;
    float2* rope = nullptr;
    cudaGetSymbolAddress((void**)&qkv, g_qkv_h);
    cudaGetSymbolAddress((void**)&mid, g_mid_h);
    cudaGetSymbolAddress((void**)&xh, g_x_h);
    cudaGetSymbolAddress((void**)&wt, g_wt_h);
    cudaGetSymbolAddress((void**)&rope, g_rope);
    __half* wt_qkv = wt;
    __half* wt_out = wt + 3145728UL;

    cudaFuncSetAttribute(gemm_h<true>, cudaFuncAttributeMaxDynamicSharedMemorySize, GEMM_SMEM);
    cudaFuncSetAttribute(gemm_h<false>, cudaFuncAttributeMaxDynamicSharedMemorySize, GEMM_SMEM);
    cudaFuncSetAttribute(attn_kernel, cudaFuncAttributeMaxDynamicSharedMemorySize,
                         (int)sizeof(AttnSmem));

    const int M = 36864, K = 1024;

    convert_x_kernel<<<(M * K / 8 + 255) / 256, 256>>>((const float4*)x, (uint4*)xh, M * K / 8);
    transpose_half_kernel<<<dim3(3072 / 32, 1024 / 32), 256>>>(W_qkv, wt_qkv, 1024, 3072);
    transpose_half_kernel<<<dim3(1024 / 32, 1024 / 32), 256>>>(W_out, wt_out, 1024, 1024);
    rope_table_kernel<<<1, 1024>>>(inv_freq, rope);

    gemm_h<true><<<dim3(3072 / 128, M / 128), 256, GEMM_SMEM>>>(
        3072, K, xh, wt_qkv, qkv, nullptr);

    attn_kernel<<<18432, 256, sizeof(AttnSmem)>>>(
        qkv, mem, z, mem_beta, rope, mid, nmem, nz);

    gemm_h<false><<<dim3(1024 / 128, M / 128), 256, GEMM_SMEM>>>(
        1024, K, mid, wt_out, x_out, b_out);
}

// round 11
// speedup vs baseline: 1.1686x; 1.1686x over previous
#include <cuda_runtime.h>
#include <cuda_fp16.h>
#include <math.h>
#include <stdint.h>

// ---------------- scratch (no allocations allowed) ----------------
__device__ __half g_qkv_h[113246208UL];  // 36864 x 3072 (GEMM1 out, fp16)
__device__ __half g_mid_h[37748736UL];   // 36864 x 1024 (attn out, fp16)
__device__ __half g_x_h[37748736UL];     // x converted to fp16
__device__ __half g_wt_h[4194304UL];     // Wt_qkv [3072,1024] + Wt_out [1024,1024]
__device__ float2 g_rope[1024];          // cos/sin(t * inv_freq[j])

__device__ __forceinline__ float sigma_fn(float x) {
    return x > 0.f ? x + 1.f : __expf(x);
}
__device__ __forceinline__ void cp_async16(uint32_t saddr, const void* gptr) {
    asm volatile("cp.async.cg.shared.global [%0], [%1], 16;\n" :: "r"(saddr), "l"(gptr));
}
__device__ __forceinline__ uint32_t smem_u32(const void* p) {
    uint32_t a;
    asm("{ .reg .u64 t; cvta.to.shared.u64 t, %1; cvt.u32.u64 %0, t; }" : "=r"(a) : "l"(p));
    return a;
}
#define LDSM4(r0, r1, r2, r3, addr) \
    asm volatile("ldmatrix.sync.aligned.m8n8.x4.shared.b16 {%0,%1,%2,%3}, [%4];" \
                 : "=r"(r0), "=r"(r1), "=r"(r2), "=r"(r3) : "r"(addr))
#define MMA16816(d0, d1, d2, d3, a0, a1, a2, a3, b0, b1) \
    asm volatile("mma.sync.aligned.m16n8k16.row.col.f32.f16.f16.f32 " \
                 "{%0,%1,%2,%3}, {%4,%5,%6,%7}, {%8,%9}, {%0,%1,%2,%3};\n" \
                 : "+f"(d0), "+f"(d1), "+f"(d2), "+f"(d3) \
                 : "r"(a0), "r"(a1), "r"(a2), "r"(a3), "r"(b0), "r"(b1))

// ================= fp16 mma.sync GEMM, ldmatrix + SW128 (round 9, proven) =====
#define A_ST 16384
#define STG  32768
#define NST  3
#define GEMM_SMEM (NST * STG)

template<bool HALF_OUT>
__global__ __launch_bounds__(256, 2)
void gemm_h(int N, int K,
            const __half* __restrict__ A,
            const __half* __restrict__ Bt,
            void* __restrict__ Cout,
            const float* __restrict__ bias)
{
    extern __shared__ char smem[];
    const uint32_t sbase = smem_u32(smem);
    const int tid  = threadIdx.x;
    const int warp = tid >> 5;
    const int lane = tid & 31;
    const int g    = lane >> 2;
    const int t4   = lane & 3;
    const int wm0  = (warp & 1) * 64;
    const int wn0  = (warp >> 1) * 32;

    const size_t m0 = (size_t)blockIdx.y * 128;
    const size_t n0 = (size_t)blockIdx.x * 128;

    const int lrow = tid >> 3;
    const int lc8  = tid & 7;
    const __half* gA = A  + (m0 + lrow) * K + lc8 * 8;
    const __half* gB = Bt + (n0 + lrow) * K + lc8 * 8;
    const uint32_t stA = lrow * 128 + ((lc8 ^ (lrow & 7)) << 4);
    const uint32_t stB = stA + A_ST;

    uint32_t abase[4], bbase[2];
    {
        const uint32_t sw = (((lane >> 4) ^ (lane & 7)) << 4);
        #pragma unroll
        for (int mt = 0; mt < 4; mt++)
            abase[mt] = (wm0 + mt * 16 + (lane & 15)) * 128 + sw;
        #pragma unroll
        for (int p = 0; p < 2; p++)
            bbase[p] = A_ST + (wn0 + p * 16 + (lane & 15)) * 128 + sw;
    }

    const int nch = K >> 6;

    float acc[4][4][4];
    #pragma unroll
    for (int i = 0; i < 4; i++)
        #pragma unroll
        for (int j = 0; j < 4; j++)
            #pragma unroll
            for (int r = 0; r < 4; r++) acc[i][j][r] = 0.f;

    #pragma unroll
    for (int s = 0; s < 2; s++) {
        #pragma unroll
        for (int u = 0; u < 4; u++) {
            cp_async16(sbase + stA + s * STG + u * 4096, gA + (size_t)u * 32 * K + s * 64);
            cp_async16(sbase + stB + s * STG + u * 4096, gB + (size_t)u * 32 * K + s * 64);
        }
        asm volatile("cp.async.commit_group;\n");
    }

    for (int c = 0; c < nch; c++) {
        asm volatile("cp.async.wait_group 1;\n");
        __syncthreads();

        const int nc = c + 2;
        if (nc < nch) {
            const int ns = nc % 3;
            #pragma unroll
            for (int u = 0; u < 4; u++) {
                cp_async16(sbase + stA + ns * STG + u * 4096, gA + (size_t)u * 32 * K + nc * 64);
                cp_async16(sbase + stB + ns * STG + u * 4096, gB + (size_t)u * 32 * K + nc * 64);
            }
        }
        asm volatile("cp.async.commit_group;\n");

        const uint32_t so = sbase + (c % 3) * STG;

        #pragma unroll
        for (int ks = 0; ks < 4; ks++) {
            const uint32_t kx = (uint32_t)ks << 5;
            uint32_t a[4][4], b[4][2];
            #pragma unroll
            for (int mt = 0; mt < 4; mt++)
                LDSM4(a[mt][0], a[mt][1], a[mt][2], a[mt][3], so + (abase[mt] ^ kx));
            #pragma unroll
            for (int p = 0; p < 2; p++)
                LDSM4(b[2 * p][0], b[2 * p + 1][0], b[2 * p][1], b[2 * p + 1][1],
                      so + (bbase[p] ^ kx));
            #pragma unroll
            for (int mt = 0; mt < 4; mt++)
                #pragma unroll
                for (int nt = 0; nt < 4; nt++)
                    MMA16816(acc[mt][nt][0], acc[mt][nt][1], acc[mt][nt][2], acc[mt][nt][3],
                             a[mt][0], a[mt][1], a[mt][2], a[mt][3], b[nt][0], b[nt][1]);
        }
    }

    #pragma unroll
    for (int mt = 0; mt < 4; mt++) {
        const size_t r0 = m0 + wm0 + mt * 16 + g;
        const size_t r1 = r0 + 8;
        #pragma unroll
        for (int nt = 0; nt < 4; nt++) {
            const int col = (int)n0 + wn0 + nt * 8 + t4 * 2;
            if (HALF_OUT) {
                __half* C = (__half*)Cout;
                *(__half2*)(C + r0 * N + col) = __floats2half2_rn(acc[mt][nt][0], acc[mt][nt][1]);
                *(__half2*)(C + r1 * N + col) = __floats2half2_rn(acc[mt][nt][2], acc[mt][nt][3]);
            } else {
                float* C = (float*)Cout;
                float b0 = bias ? bias[col] : 0.f;
                float b1 = bias ? bias[col + 1] : 0.f;
                *(float2*)(C + r0 * N + col) = make_float2(acc[mt][nt][0] + b0, acc[mt][nt][1] + b1);
                *(float2*)(C + r1 * N + col) = make_float2(acc[mt][nt][2] + b0, acc[mt][nt][3] + b1);
            }
        }
    }
}

// ---------------- preprocessing (unchanged) ----------------
__global__ __launch_bounds__(256)
void convert_x_kernel(const float4* __restrict__ in, uint4* __restrict__ out, int n8) {
    int i = blockIdx.x * 256 + threadIdx.x;
    if (i >= n8) return;
    float4 f0 = in[2 * i], f1 = in[2 * i + 1];
    __half2 h[4];
    h[0] = __floats2half2_rn(f0.x, f0.y);
    h[1] = __floats2half2_rn(f0.z, f0.w);
    h[2] = __floats2half2_rn(f1.x, f1.y);
    h[3] = __floats2half2_rn(f1.z, f1.w);
    out[i] = *(const uint4*)h;
}

__global__ __launch_bounds__(256)
void transpose_half_kernel(const float* __restrict__ in, __half* __restrict__ out,
                           int Kk, int Nn) {
    __shared__ float t[32][33];
    const int n0 = blockIdx.x * 32;
    const int k0 = blockIdx.y * 32;
    const int tx = threadIdx.x & 31;
    const int ty = threadIdx.x >> 5;
    #pragma unroll
    for (int r = 0; r < 4; r++) {
        int kr = ty + r * 8;
        t[kr][tx] = in[(size_t)(k0 + kr) * Nn + n0 + tx];
    }
    __syncthreads();
    if (threadIdx.x < 64) {
        const int nl = threadIdx.x >> 1;
        const int kg = threadIdx.x & 1;
        __half h[16];
        #pragma unroll
        for (int o = 0; o < 16; o++)
            h[o] = __float2half_rn(t[kg * 16 + o][nl]);
        uint4* o4 = (uint4*)(out + (size_t)(n0 + nl) * Kk + k0 + kg * 16);
        o4[0] = ((const uint4*)h)[0];
        o4[1] = ((const uint4*)h)[1];
    }
}

__global__ void rope_table_kernel(const float* __restrict__ inv_freq,
                                  float2* __restrict__ tab) {
    int t = threadIdx.x >> 5, j = threadIdx.x & 31;
    float sn, cs;
    sincosf((float)t * inv_freq[j], &sn, &cs);
    tab[t * 32 + j] = make_float2(cs, sn);
}

// ---------------- fused attention (round-9 logic, smem shrunk for 4 CTAs/SM) ----
#define TSEQ 32
#define DHD 64
#define P 68

struct __align__(16) AttnSmem {
    float qs[TSEQ][P];      // 8704
    float ks[TSEQ][P];      // 8704
    float vs[TSEQ][P];      // 8704
    float ms[DHD][DHD];     // 16384 (all reads broadcast or stride-1 -> no pad needed)
    float sc[TSEQ][33];     // 4224
    float sqT[DHD][33];     // 8448
    float skk[8][P];        // 2176
    float zs[DHD];          // 256
    float denom[TSEQ];      // 128
};                          // total 57728 B -> 4 CTAs/SM

__global__ __launch_bounds__(256, 4)
void attn_kernel(const __half* __restrict__ qkv,
                 const float* __restrict__ mem,
                 const float* __restrict__ zin,
                 const float* __restrict__ mem_beta,
                 const float2* __restrict__ rope_tab,
                 __half* __restrict__ out_mid,
                 float* __restrict__ new_mem,
                 float* __restrict__ new_z)
{
    extern __shared__ __align__(16) char smem_raw[];
    AttnSmem& S = *(AttnSmem*)smem_raw;

    const int bh   = blockIdx.x;
    const int s    = bh >> 4;
    const int head = bh & 15;
    const int b    = s / 576;
    const int rem  = s - b * 576;
    const int tid  = threadIdx.x;
    const int warp = tid >> 5;
    const int lane = tid & 31;
    const int row_base = b * 18432 + rem;
    const size_t mbase = (size_t)bh * (DHD * DHD);

    const float g = 1.f / (1.f + __expf(-mem_beta[head]));
    const float ig = 1.f - g;

    // ---- phase 1: load qkv (half2), mem, z ----
    for (int e = tid; e < 1024; e += 256) {
        int t = e >> 5, d2 = (e & 31) * 2;
        size_t base = (size_t)(row_base + t * 576) * 3072 + head * 64 + d2;
        float2 q = __half22float2(*(const __half2*)(qkv + base));
        float2 k = __half22float2(*(const __half2*)(qkv + base + 1024));
        float2 v = __half22float2(*(const __half2*)(qkv + base + 2048));
        S.qs[t][d2] = q.x; S.qs[t][d2 + 1] = q.y;
        S.ks[t][d2] = k.x; S.ks[t][d2 + 1] = k.y;
        S.vs[t][d2] = v.x; S.vs[t][d2 + 1] = v.y;
    }
    for (int e = tid; e < 4096; e += 256)
        ((float*)S.ms)[e] = mem[mbase + e];
    if (tid < DHD) S.zs[tid] = zin[(size_t)bh * DHD + tid];
    __syncthreads();

    // ---- phase 2: skk = sigma(sigma(k_raw[:8])) ; new_z ----
    for (int e = tid; e < 8 * DHD; e += 256) {
        int t = e >> 6, i = e & 63;
        S.skk[t][i] = sigma_fn(sigma_fn(S.ks[t][i]));
    }
    if (tid < DHD) {
        float acc = S.zs[tid];
        #pragma unroll
        for (int t = 0; t < TSEQ; t++) acc += sigma_fn(S.ks[t][tid]);
        new_z[(size_t)bh * DHD + tid] = acc;
    }
    __syncthreads();

    // ---- phase 3: new_mem + rotary (rope read straight from L2) ----
    for (int e = tid; e < 4096; e += 256) {
        int i = e >> 6, j = e & 63;
        float acc = S.ms[i][j];
        #pragma unroll
        for (int t = 0; t < 8; t++) acc += S.skk[t][i] * S.vs[t][j];
        new_mem[mbase + e] = acc;
    }
    for (int e = tid; e < 1024; e += 256) {
        int t = e >> 5, j = e & 31;
        float2 cssn = rope_tab[e];
        float q0 = S.qs[t][2 * j], q1 = S.qs[t][2 * j + 1];
        S.qs[t][2 * j]     = q0 * cssn.x - q1 * cssn.y;
        S.qs[t][2 * j + 1] = q1 * cssn.x + q0 * cssn.y;
        float k0 = S.ks[t][2 * j], k1 = S.ks[t][2 * j + 1];
        S.ks[t][2 * j]     = k0 * cssn.x - k1 * cssn.y;
        S.ks[t][2 * j + 1] = k1 * cssn.x + k0 * cssn.y;
    }
    __syncthreads();

    // ---- phase 4: scores + sigma_q -> sqT ----
    {
        const int tr = tid >> 4;
        const int tc = tid & 15;
        float a00 = 0.f, a01 = 0.f, a10 = 0.f, a11 = 0.f;
        #pragma unroll
        for (int d = 0; d < DHD; d += 4) {
            float4 q0 = *(const float4*)&S.qs[tr][d];
            float4 q1 = *(const float4*)&S.qs[tr + 16][d];
            float4 k0 = *(const float4*)&S.ks[tc][d];
            float4 k1 = *(const float4*)&S.ks[tc + 16][d];
            a00 += q0.x * k0.x + q0.y * k0.y + q0.z * k0.z + q0.w * k0.w;
            a01 += q0.x * k1.x + q0.y * k1.y + q0.z * k1.z + q0.w * k1.w;
            a10 += q1.x * k0.x + q1.y * k0.y + q1.z * k0.z + q1.w * k0.w;
            a11 += q1.x * k1.x + q1.y * k1.y + q1.z * k1.z + q1.w * k1.w;
        }
        S.sc[tr][tc]           = a00 * 0.125f;
        S.sc[tr][tc + 16]      = a01 * 0.125f;
        S.sc[tr + 16][tc]      = a10 * 0.125f;
        S.sc[tr + 16][tc + 16] = a11 * 0.125f;
    }
    for (int e = tid; e < 2048; e += 256) {
        int t = e >> 6, dd = e & 63;
        S.sqT[dd][t] = sigma_fn(S.qs[t][dd]);
    }
    __syncthreads();

    // ---- phase 5: warp-parallel softmax + denom ----
    #pragma unroll
    for (int r = 0; r < 4; r++) {
        int t = warp * 4 + r;
        float v = (lane <= t) ? S.sc[t][lane] : -1e30f;
        float m = v;
        #pragma unroll
        for (int o = 16; o > 0; o >>= 1) m = fmaxf(m, __shfl_xor_sync(0xFFFFFFFFu, m, o));
        float ex = (lane <= t) ? __expf(v - m) : 0.f;
        float ssum = ex;
        #pragma unroll
        for (int o = 16; o > 0; o >>= 1) ssum += __shfl_xor_sync(0xFFFFFFFFu, ssum, o);
        S.sc[t][lane] = ex / ssum;
    }
    if (tid < TSEQ) {
        float acc = 0.f;
        #pragma unroll
        for (int kx = 0; kx < DHD; kx++) acc += S.sqT[kx][tid] * S.zs[kx];
        S.denom[tid] = acc;
    }
    __syncthreads();

    // ---- phase 6: out = g*(sigma_q@mem)/denom + (1-g)*(attn@v) ----
    {
        const int dc = warp;
        const int t  = lane;
        const int dd0 = dc * 8;
        float4 aA0 = {0,0,0,0}, aA1 = {0,0,0,0};
        float4 aR0 = {0,0,0,0}, aR1 = {0,0,0,0};
        #pragma unroll
        for (int tt = 0; tt < TSEQ; tt++) {
            float sv = S.sc[t][tt];
            float4 v0 = *(const float4*)&S.vs[tt][dd0];
            float4 v1 = *(const float4*)&S.vs[tt][dd0 + 4];
            aA0.x += sv * v0.x; aA0.y += sv * v0.y; aA0.z += sv * v0.z; aA0.w += sv * v0.w;
            aA1.x += sv * v1.x; aA1.y += sv * v1.y; aA1.z += sv * v1.z; aA1.w += sv * v1.w;
        }
        #pragma unroll
        for (int kx = 0; kx < DHD; kx++) {
            float sq = S.sqT[kx][t];
            float4 m0 = *(const float4*)&S.ms[kx][dd0];
            float4 m1 = *(const float4*)&S.ms[kx][dd0 + 4];
            aR0.x += sq * m0.x; aR0.y += sq * m0.y; aR0.z += sq * m0.z; aR0.w += sq * m0.w;
            aR1.x += sq * m1.x; aR1.y += sq * m1.y; aR1.z += sq * m1.z; aR1.w += sq * m1.w;
        }
        const float gi = g / S.denom[t];
        float4 o0, o1;
        o0.x = gi * aR0.x + ig * aA0.x;  o0.y = gi * aR0.y + ig * aA0.y;
        o0.z = gi * aR0.z + ig * aA0.z;  o0.w = gi * aR0.w + ig * aA0.w;
        o1.x = gi * aR1.x + ig * aA1.x;  o1.y = gi * aR1.y + ig * aA1.y;
        o1.z = gi * aR1.z + ig * aA1.z;  o1.w = gi * aR1.w + ig * aA1.w;
        *(float4*)&S.qs[t][dd0]     = o0;
        *(float4*)&S.qs[t][dd0 + 4] = o1;
    }
    __syncthreads();

    // ---- phase 7: coalesced fp16 writeback ----
    for (int e = tid; e < 1024; e += 256) {
        int t = e >> 5, dd = (e & 31) * 2;
        __half2 h = __floats2half2_rn(S.qs[t][dd], S.qs[t][dd + 1]);
        *(__half2*)(out_mid + (size_t)(row_base + t * 576) * 1024 + head * 64 + dd) = h;
    }
}

// ---------------- launch ----------------
extern "C" void kernel_launch(void* const* d_in, const int* in_sizes, int n_in,
                              void* d_out, int out_size) {
    const float* x        = (const float*)d_in[0];
    const float* mem      = (const float*)d_in[1];
    const float* z        = (const float*)d_in[2];
    const float* W_qkv    = (const float*)d_in[3];
    const float* W_out    = (const float*)d_in[4];
    const float* b_out    = (const float*)d_in[5];
    const float* mem_beta = (const float*)d_in[6];
    const float* inv_freq = (const float*)d_in[7];

    float* x_out = (float*)d_out;
    float* nmem  = x_out + 37748736UL;
    float* nz    = x_out + 113246208UL;

    __half *qkv = nullptr, *mid = nullptr, *xh = nullptr, *wt = nullptr;
    float2* rope = nullptr;
    cudaGetSymbolAddress((void**)&qkv, g_qkv_h);
    cudaGetSymbolAddress((void**)&mid, g_mid_h);
    cudaGetSymbolAddress((void**)&xh, g_x_h);
    cudaGetSymbolAddress((void**)&wt, g_wt_h);
    cudaGetSymbolAddress((void**)&rope, g_rope);
    __half* wt_qkv = wt;
    __half* wt_out = wt + 3145728UL;

    cudaFuncSetAttribute(gemm_h<true>, cudaFuncAttributeMaxDynamicSharedMemorySize, GEMM_SMEM);
    cudaFuncSetAttribute(gemm_h<false>, cudaFuncAttributeMaxDynamicSharedMemorySize, GEMM_SMEM);
    cudaFuncSetAttribute(attn_kernel, cudaFuncAttributeMaxDynamicSharedMemorySize,
                         (int)sizeof(AttnSmem));

    const int M = 36864, K = 1024;

    convert_x_kernel<<<(M * K / 8 + 255) / 256, 256>>>((const float4*)x, (uint4*)xh, M * K / 8);
    transpose_half_kernel<<<dim3(3072 / 32, 1024 / 32), 256>>>(W_qkv, wt_qkv, 1024, 3072);
    transpose_half_kernel<<<dim3(1024 / 32, 1024 / 32), 256>>>(W_out, wt_out, 1024, 1024);
    rope_table_kernel<<<1, 1024>>>(inv_freq, rope);

    gemm_h<true><<<dim3(3072 / 128, M / 128), 256, GEMM_SMEM>>>(
        3072, K, xh, wt_qkv, qkv, nullptr);

    attn_kernel<<<18432, 256, sizeof(AttnSmem)>>>(
        qkv, mem, z, mem_beta, rope, mid, nmem, nz);

    gemm_h<false><<<dim3(1024 / 128, M / 128), 256, GEMM_SMEM>>>(
        1024, K, mid, wt_out, x_out, b_out);
}

// round 12
// speedup vs baseline: 1.2191x; 1.0432x over previous
#include <cuda_runtime.h>
#include <cuda_fp16.h>
#include <math.h>
#include <stdint.h>

// ---------------- scratch (no allocations allowed) ----------------
__device__ __half g_qkv_h[113246208UL];  // 36864 x 3072 (GEMM1 out, fp16)
__device__ __half g_mid_h[37748736UL];   // 36864 x 1024 (attn out, fp16)
__device__ __half g_x_h[37748736UL];     // x converted to fp16
__device__ __half g_wt_h[4194304UL];     // Wt_qkv [3072,1024] + Wt_out [1024,1024]
__device__ float2 g_rope[1024];          // cos/sin(t * inv_freq[j])

__device__ __forceinline__ float sigma_fn(float x) {
    return x > 0.f ? x + 1.f : __expf(x);
}
__device__ __forceinline__ void cp_async16(uint32_t saddr, const void* gptr) {
    asm volatile("cp.async.cg.shared.global [%0], [%1], 16;\n" :: "r"(saddr), "l"(gptr));
}
__device__ __forceinline__ uint32_t smem_u32(const void* p) {
    uint32_t a;
    asm("{ .reg .u64 t; cvta.to.shared.u64 t, %1; cvt.u32.u64 %0, t; }" : "=r"(a) : "l"(p));
    return a;
}
#define LDSM4(r0, r1, r2, r3, addr) \
    asm volatile("ldmatrix.sync.aligned.m8n8.x4.shared.b16 {%0,%1,%2,%3}, [%4];" \
                 : "=r"(r0), "=r"(r1), "=r"(r2), "=r"(r3) : "r"(addr))
#define MMA16816(d0, d1, d2, d3, a0, a1, a2, a3, b0, b1) \
    asm volatile("mma.sync.aligned.m16n8k16.row.col.f32.f16.f16.f32 " \
                 "{%0,%1,%2,%3}, {%4,%5,%6,%7}, {%8,%9}, {%0,%1,%2,%3};\n" \
                 : "+f"(d0), "+f"(d1), "+f"(d2), "+f"(d3) \
                 : "r"(a0), "r"(a1), "r"(a2), "r"(a3), "r"(b0), "r"(b1))

// ================= fp16 mma.sync GEMM, ldmatrix + SW128 (round 9, proven) =====
#define A_ST 16384
#define STG  32768
#define NST  3
#define GEMM_SMEM (NST * STG)

template<bool HALF_OUT>
__global__ __launch_bounds__(256, 2)
void gemm_h(int N, int K,
            const __half* __restrict__ A,
            const __half* __restrict__ Bt,
            void* __restrict__ Cout,
            const float* __restrict__ bias)
{
    extern __shared__ char smem[];
    const uint32_t sbase = smem_u32(smem);
    const int tid  = threadIdx.x;
    const int warp = tid >> 5;
    const int lane = tid & 31;
    const int g    = lane >> 2;
    const int t4   = lane & 3;
    const int wm0  = (warp & 1) * 64;
    const int wn0  = (warp >> 1) * 32;

    const size_t m0 = (size_t)blockIdx.y * 128;
    const size_t n0 = (size_t)blockIdx.x * 128;

    const int lrow = tid >> 3;
    const int lc8  = tid & 7;
    const __half* gA = A  + (m0 + lrow) * K + lc8 * 8;
    const __half* gB = Bt + (n0 + lrow) * K + lc8 * 8;
    const uint32_t stA = lrow * 128 + ((lc8 ^ (lrow & 7)) << 4);
    const uint32_t stB = stA + A_ST;

    uint32_t abase[4], bbase[2];
    {
        const uint32_t sw = (((lane >> 4) ^ (lane & 7)) << 4);
        #pragma unroll
        for (int mt = 0; mt < 4; mt++)
            abase[mt] = (wm0 + mt * 16 + (lane & 15)) * 128 + sw;
        #pragma unroll
        for (int p = 0; p < 2; p++)
            bbase[p] = A_ST + (wn0 + p * 16 + (lane & 15)) * 128 + sw;
    }

    const int nch = K >> 6;

    float acc[4][4][4];
    #pragma unroll
    for (int i = 0; i < 4; i++)
        #pragma unroll
        for (int j = 0; j < 4; j++)
            #pragma unroll
            for (int r = 0; r < 4; r++) acc[i][j][r] = 0.f;

    #pragma unroll
    for (int s = 0; s < 2; s++) {
        #pragma unroll
        for (int u = 0; u < 4; u++) {
            cp_async16(sbase + stA + s * STG + u * 4096, gA + (size_t)u * 32 * K + s * 64);
            cp_async16(sbase + stB + s * STG + u * 4096, gB + (size_t)u * 32 * K + s * 64);
        }
        asm volatile("cp.async.commit_group;\n");
    }

    for (int c = 0; c < nch; c++) {
        asm volatile("cp.async.wait_group 1;\n");
        __syncthreads();

        const int nc = c + 2;
        if (nc < nch) {
            const int ns = nc % 3;
            #pragma unroll
            for (int u = 0; u < 4; u++) {
                cp_async16(sbase + stA + ns * STG + u * 4096, gA + (size_t)u * 32 * K + nc * 64);
                cp_async16(sbase + stB + ns * STG + u * 4096, gB + (size_t)u * 32 * K + nc * 64);
            }
        }
        asm volatile("cp.async.commit_group;\n");

        const uint32_t so = sbase + (c % 3) * STG;

        #pragma unroll
        for (int ks = 0; ks < 4; ks++) {
            const uint32_t kx = (uint32_t)ks << 5;
            uint32_t a[4][4], b[4][2];
            #pragma unroll
            for (int mt = 0; mt < 4; mt++)
                LDSM4(a[mt][0], a[mt][1], a[mt][2], a[mt][3], so + (abase[mt] ^ kx));
            #pragma unroll
            for (int p = 0; p < 2; p++)
                LDSM4(b[2 * p][0], b[2 * p + 1][0], b[2 * p][1], b[2 * p + 1][1],
                      so + (bbase[p] ^ kx));
            #pragma unroll
            for (int mt = 0; mt < 4; mt++)
                #pragma unroll
                for (int nt = 0; nt < 4; nt++)
                    MMA16816(acc[mt][nt][0], acc[mt][nt][1], acc[mt][nt][2], acc[mt][nt][3],
                             a[mt][0], a[mt][1], a[mt][2], a[mt][3], b[nt][0], b[nt][1]);
        }
    }

    #pragma unroll
    for (int mt = 0; mt < 4; mt++) {
        const size_t r0 = m0 + wm0 + mt * 16 + g;
        const size_t r1 = r0 + 8;
        #pragma unroll
        for (int nt = 0; nt < 4; nt++) {
            const int col = (int)n0 + wn0 + nt * 8 + t4 * 2;
            if (HALF_OUT) {
                __half* C = (__half*)Cout;
                *(__half2*)(C + r0 * N + col) = __floats2half2_rn(acc[mt][nt][0], acc[mt][nt][1]);
                *(__half2*)(C + r1 * N + col) = __floats2half2_rn(acc[mt][nt][2], acc[mt][nt][3]);
            } else {
                float* C = (float*)Cout;
                float b0 = bias ? bias[col] : 0.f;
                float b1 = bias ? bias[col + 1] : 0.f;
                *(float2*)(C + r0 * N + col) = make_float2(acc[mt][nt][0] + b0, acc[mt][nt][1] + b1);
                *(float2*)(C + r1 * N + col) = make_float2(acc[mt][nt][2] + b0, acc[mt][nt][3] + b1);
            }
        }
    }
}

// ---------------- preprocessing: convert x (+rope table in block 0) ----------------
__global__ __launch_bounds__(256)
void convert_x_kernel(const float4* __restrict__ in, uint4* __restrict__ out, int n8,
                      const float* __restrict__ inv_freq, float2* __restrict__ rope) {
    if (blockIdx.x == 0) {
        for (int e = threadIdx.x; e < 1024; e += 256) {
            int t = e >> 5, j = e & 31;
            float sn, cs;
            sincosf((float)t * inv_freq[j], &sn, &cs);
            rope[e] = make_float2(cs, sn);
        }
    }
    int i = blockIdx.x * 256 + threadIdx.x;
    if (i >= n8) return;
    float4 f0 = in[2 * i], f1 = in[2 * i + 1];
    __half2 h[4];
    h[0] = __floats2half2_rn(f0.x, f0.y);
    h[1] = __floats2half2_rn(f0.z, f0.w);
    h[2] = __floats2half2_rn(f1.x, f1.y);
    h[3] = __floats2half2_rn(f1.z, f1.w);
    out[i] = *(const uint4*)h;
}

// transpose BOTH weights in one launch: tiles [0,3072) -> W_qkv, [3072,4096) -> W_out
__global__ __launch_bounds__(256)
void transpose_both_kernel(const float* __restrict__ Wq, const float* __restrict__ Wo,
                           __half* __restrict__ outq, __half* __restrict__ outo) {
    __shared__ float t[32][33];
    int bid = blockIdx.x;
    const float* in;
    __half* out;
    int Nn, n0, k0;
    const int Kk = 1024;
    if (bid < 3072) {
        in = Wq; out = outq; Nn = 3072;
        n0 = (bid % 96) * 32; k0 = (bid / 96) * 32;
    } else {
        bid -= 3072;
        in = Wo; out = outo; Nn = 1024;
        n0 = (bid % 32) * 32; k0 = (bid / 32) * 32;
    }
    const int tx = threadIdx.x & 31;
    const int ty = threadIdx.x >> 5;
    #pragma unroll
    for (int r = 0; r < 4; r++) {
        int kr = ty + r * 8;
        t[kr][tx] = in[(size_t)(k0 + kr) * Nn + n0 + tx];
    }
    __syncthreads();
    if (threadIdx.x < 64) {
        const int nl = threadIdx.x >> 1;
        const int kg = threadIdx.x & 1;
        __half h[16];
        #pragma unroll
        for (int o = 0; o < 16; o++)
            h[o] = __float2half_rn(t[kg * 16 + o][nl]);
        uint4* o4 = (uint4*)(out + (size_t)(n0 + nl) * Kk + k0 + kg * 16);
        o4[0] = ((const uint4*)h)[0];
        o4[1] = ((const uint4*)h)[1];
    }
}

// ---------------- fused attention (round-9 passing version, verbatim) ----------
#define TSEQ 32
#define DHD 64
#define P 68

struct AttnSmem {
    float qs[TSEQ][P];
    float ks[TSEQ][P];
    float vs[TSEQ][P];
    float ms[DHD][P];
    float sc[TSEQ][33];
    float sqT[DHD][33];
    float skk[8][P];
    float2 rope[TSEQ][32];
    float zs[DHD];
    float denom[TSEQ];
};

__global__ __launch_bounds__(256)
void attn_kernel(const __half* __restrict__ qkv,
                 const float* __restrict__ mem,
                 const float* __restrict__ zin,
                 const float* __restrict__ mem_beta,
                 const float2* __restrict__ rope_tab,
                 __half* __restrict__ out_mid,
                 float* __restrict__ new_mem,
                 float* __restrict__ new_z)
{
    extern __shared__ char smem_raw[];
    AttnSmem& S = *(AttnSmem*)smem_raw;

    const int bh   = blockIdx.x;
    const int s    = bh >> 4;
    const int head = bh & 15;
    const int b    = s / 576;
    const int rem  = s - b * 576;
    const int tid  = threadIdx.x;
    const int warp = tid >> 5;
    const int lane = tid & 31;
    const int row_base = b * 18432 + rem;
    const size_t mbase = (size_t)bh * (DHD * DHD);

    const float g = 1.f / (1.f + __expf(-mem_beta[head]));
    const float ig = 1.f - g;

    // ---- phase 1: load qkv (half2), mem, z, rope table ----
    for (int e = tid; e < 1024; e += 256) {
        int t = e >> 5, d2 = (e & 31) * 2;
        size_t base = (size_t)(row_base + t * 576) * 3072 + head * 64 + d2;
        float2 q = __half22float2(*(const __half2*)(qkv + base));
        float2 k = __half22float2(*(const __half2*)(qkv + base + 1024));
        float2 v = __half22float2(*(const __half2*)(qkv + base + 2048));
        S.qs[t][d2] = q.x; S.qs[t][d2 + 1] = q.y;
        S.ks[t][d2] = k.x; S.ks[t][d2 + 1] = k.y;
        S.vs[t][d2] = v.x; S.vs[t][d2 + 1] = v.y;
        ((float2*)S.rope)[e] = rope_tab[e];
    }
    for (int e = tid; e < 4096; e += 256)
        S.ms[e >> 6][e & 63] = mem[mbase + e];
    if (tid < DHD) S.zs[tid] = zin[(size_t)bh * DHD + tid];
    __syncthreads();

    // ---- phase 2: skk = sigma(sigma(k_raw[:8])) ; new_z ----
    for (int e = tid; e < 8 * DHD; e += 256) {
        int t = e >> 6, i = e & 63;
        S.skk[t][i] = sigma_fn(sigma_fn(S.ks[t][i]));
    }
    if (tid < DHD) {
        float acc = S.zs[tid];
        #pragma unroll
        for (int t = 0; t < TSEQ; t++) acc += sigma_fn(S.ks[t][tid]);
        new_z[(size_t)bh * DHD + tid] = acc;
    }
    __syncthreads();

    // ---- phase 3: new_mem + rotary ----
    for (int e = tid; e < 4096; e += 256) {
        int i = e >> 6, j = e & 63;
        float acc = S.ms[i][j];
        #pragma unroll
        for (int t = 0; t < 8; t++) acc += S.skk[t][i] * S.vs[t][j];
        new_mem[mbase + e] = acc;
    }
    for (int e = tid; e < 1024; e += 256) {
        int t = e >> 5, j = e & 31;
        float2 cssn = S.rope[t][j];
        float q0 = S.qs[t][2 * j], q1 = S.qs[t][2 * j + 1];
        S.qs[t][2 * j]     = q0 * cssn.x - q1 * cssn.y;
        S.qs[t][2 * j + 1] = q1 * cssn.x + q0 * cssn.y;
        float k0 = S.ks[t][2 * j], k1 = S.ks[t][2 * j + 1];
        S.ks[t][2 * j]     = k0 * cssn.x - k1 * cssn.y;
        S.ks[t][2 * j + 1] = k1 * cssn.x + k0 * cssn.y;
    }
    __syncthreads();

    // ---- phase 4: scores + sigma_q -> sqT ----
    {
        const int tr = tid >> 4;
        const int tc = tid & 15;
        float a00 = 0.f, a01 = 0.f, a10 = 0.f, a11 = 0.f;
        #pragma unroll
        for (int d = 0; d < DHD; d += 4) {
            float4 q0 = *(const float4*)&S.qs[tr][d];
            float4 q1 = *(const float4*)&S.qs[tr + 16][d];
            float4 k0 = *(const float4*)&S.ks[tc][d];
            float4 k1 = *(const float4*)&S.ks[tc + 16][d];
            a00 += q0.x * k0.x + q0.y * k0.y + q0.z * k0.z + q0.w * k0.w;
            a01 += q0.x * k1.x + q0.y * k1.y + q0.z * k1.z + q0.w * k1.w;
            a10 += q1.x * k0.x + q1.y * k0.y + q1.z * k0.z + q1.w * k0.w;
            a11 += q1.x * k1.x + q1.y * k1.y + q1.z * k1.z + q1.w * k1.w;
        }
        S.sc[tr][tc]           = a00 * 0.125f;
        S.sc[tr][tc + 16]      = a01 * 0.125f;
        S.sc[tr + 16][tc]      = a10 * 0.125f;
        S.sc[tr + 16][tc + 16] = a11 * 0.125f;
    }
    for (int e = tid; e < 2048; e += 256) {
        int t = e >> 6, dd = e & 63;
        S.sqT[dd][t] = sigma_fn(S.qs[t][dd]);
    }
    __syncthreads();

    // ---- phase 5: warp-parallel softmax + denom ----
    #pragma unroll
    for (int r = 0; r < 4; r++) {
        int t = warp * 4 + r;
        float v = (lane <= t) ? S.sc[t][lane] : -1e30f;
        float m = v;
        #pragma unroll
        for (int o = 16; o > 0; o >>= 1) m = fmaxf(m, __shfl_xor_sync(0xFFFFFFFFu, m, o));
        float ex = (lane <= t) ? __expf(v - m) : 0.f;
        float ssum = ex;
        #pragma unroll
        for (int o = 16; o > 0; o >>= 1) ssum += __shfl_xor_sync(0xFFFFFFFFu, ssum, o);
        S.sc[t][lane] = ex / ssum;
    }
    if (tid < TSEQ) {
        float acc = 0.f;
        #pragma unroll
        for (int kx = 0; kx < DHD; kx++) acc += S.sqT[kx][tid] * S.zs[kx];
        S.denom[tid] = acc;
    }
    __syncthreads();

    // ---- phase 6: out = g*(sigma_q@mem)/denom + (1-g)*(attn@v) ----
    {
        const int dc = warp;
        const int t  = lane;
        const int dd0 = dc * 8;
        float4 aA0 = {0,0,0,0}, aA1 = {0,0,0,0};
        float4 aR0 = {0,0,0,0}, aR1 = {0,0,0,0};
        #pragma unroll
        for (int tt = 0; tt < TSEQ; tt++) {
            float sv = S.sc[t][tt];
            float4 v0 = *(const float4*)&S.vs[tt][dd0];
            float4 v1 = *(const float4*)&S.vs[tt][dd0 + 4];
            aA0.x += sv * v0.x; aA0.y += sv * v0.y; aA0.z += sv * v0.z; aA0.w += sv * v0.w;
            aA1.x += sv * v1.x; aA1.y += sv * v1.y; aA1.z += sv * v1.z; aA1.w += sv * v1.w;
        }
        #pragma unroll
        for (int kx = 0; kx < DHD; kx++) {
            float sq = S.sqT[kx][t];
            float4 m0 = *(const float4*)&S.ms[kx][dd0];
            float4 m1 = *(const float4*)&S.ms[kx][dd0 + 4];
            aR0.x += sq * m0.x; aR0.y += sq * m0.y; aR0.z += sq * m0.z; aR0.w += sq * m0.w;
            aR1.x += sq * m1.x; aR1.y += sq * m1.y; aR1.z += sq * m1.z; aR1.w += sq * m1.w;
        }
        const float gi = g / S.denom[t];
        float4 o0, o1;
        o0.x = gi * aR0.x + ig * aA0.x;  o0.y = gi * aR0.y + ig * aA0.y;
        o0.z = gi * aR0.z + ig * aA0.z;  o0.w = gi * aR0.w + ig * aA0.w;
        o1.x = gi * aR1.x + ig * aA1.x;  o1.y = gi * aR1.y + ig * aA1.y;
        o1.z = gi * aR1.z + ig * aA1.z;  o1.w = gi * aR1.w + ig * aA1.w;
        *(float4*)&S.qs[t][dd0]     = o0;
        *(float4*)&S.qs[t][dd0 + 4] = o1;
    }
    __syncthreads();

    // ---- phase 7: coalesced fp16 writeback ----
    for (int e = tid; e < 1024; e += 256) {
        int t = e >> 5, dd = (e & 31) * 2;
        __half2 h = __floats2half2_rn(S.qs[t][dd], S.qs[t][dd + 1]);
        *(__half2*)(out_mid + (size_t)(row_base + t * 576) * 1024 + head * 64 + dd) = h;
    }
}

// ---------------- launch ----------------
extern "C" void kernel_launch(void* const* d_in, const int* in_sizes, int n_in,
                              void* d_out, int out_size) {
    const float* x        = (const float*)d_in[0];
    const float* mem      = (const float*)d_in[1];
    const float* z        = (const float*)d_in[2];
    const float* W_qkv    = (const float*)d_in[3];
    const float* W_out    = (const float*)d_in[4];
    const float* b_out    = (const float*)d_in[5];
    const float* mem_beta = (const float*)d_in[6];
    const float* inv_freq = (const float*)d_in[7];

    float* x_out = (float*)d_out;
    float* nmem  = x_out + 37748736UL;
    float* nz    = x_out + 113246208UL;

    __half *qkv = nullptr, *mid = nullptr, *xh = nullptr, *wt = nullptr;
    float2* rope = nullptr;
    cudaGetSymbolAddress((void**)&qkv, g_qkv_h);
    cudaGetSymbolAddress((void**)&mid, g_mid_h);
    cudaGetSymbolAddress((void**)&xh, g_x_h);
    cudaGetSymbolAddress((void**)&wt, g_wt_h);
    cudaGetSymbolAddress((void**)&rope, g_rope);
    __half* wt_qkv = wt;
    __half* wt_out = wt + 3145728UL;

    cudaFuncSetAttribute(gemm_h<true>, cudaFuncAttributeMaxDynamicSharedMemorySize, GEMM_SMEM);
    cudaFuncSetAttribute(gemm_h<false>, cudaFuncAttributeMaxDynamicSharedMemorySize, GEMM_SMEM);
    cudaFuncSetAttribute(attn_kernel, cudaFuncAttributeMaxDynamicSharedMemorySize,
                         (int)sizeof(AttnSmem));

    const int M = 36864, K = 1024;

    // launch 0: convert x + rope table
    convert_x_kernel<<<(M * K / 8 + 255) / 256, 256>>>(
        (const float4*)x, (uint4*)xh, M * K / 8, inv_freq, rope);
    // launch 1: both weight transposes
    transpose_both_kernel<<<4096, 256>>>(W_qkv, W_out, wt_qkv, wt_out);
    // launch 2: GEMM1
    gemm_h<true><<<dim3(3072 / 128, M / 128), 256, GEMM_SMEM>>>(
        3072, K, xh, wt_qkv, qkv, nullptr);
    // launch 3: attention (profiler captures this index)
    attn_kernel<<<18432, 256, sizeof(AttnSmem)>>>(
        qkv, mem, z, mem_beta, rope, mid, nmem, nz);
    // launch 4: GEMM2
    gemm_h<false><<<dim3(1024 / 128, M / 128), 256, GEMM_SMEM>>>(
        1024, K, mid, wt_out, x_out, b_out);
}

// round 13
// speedup vs baseline: 1.2710x; 1.0426x over previous
#include <cuda_runtime.h>
#include <cuda_fp16.h>
#include <math.h>
#include <stdint.h>

// ---------------- scratch (no allocations allowed) ----------------
__device__ __half g_qkv_h[113246208UL];  // 36864 x 3072 (GEMM1 out, fp16)
__device__ __half g_mid_h[37748736UL];   // 36864 x 1024 (attn out, fp16)
__device__ __half g_x_h[37748736UL];     // x converted to fp16
__device__ __half g_wt_h[4194304UL];     // Wt_qkv [3072,1024] + Wt_out [1024,1024]
__device__ float2 g_rope[1024];          // cos/sin(t * inv_freq[j])

__device__ __forceinline__ float sigma_fn(float x) {
    return x > 0.f ? x + 1.f : __expf(x);
}
__device__ __forceinline__ void cp_async16(uint32_t saddr, const void* gptr) {
    asm volatile("cp.async.cg.shared.global [%0], [%1], 16;\n" :: "r"(saddr), "l"(gptr));
}
__device__ __forceinline__ uint32_t smem_u32(const void* p) {
    uint32_t a;
    asm("{ .reg .u64 t; cvta.to.shared.u64 t, %1; cvt.u32.u64 %0, t; }" : "=r"(a) : "l"(p));
    return a;
}
#define LDSM4(r0, r1, r2, r3, addr) \
    asm volatile("ldmatrix.sync.aligned.m8n8.x4.shared.b16 {%0,%1,%2,%3}, [%4];" \
                 : "=r"(r0), "=r"(r1), "=r"(r2), "=r"(r3) : "r"(addr))
#define MMA16816(d0, d1, d2, d3, a0, a1, a2, a3, b0, b1) \
    asm volatile("mma.sync.aligned.m16n8k16.row.col.f32.f16.f16.f32 " \
                 "{%0,%1,%2,%3}, {%4,%5,%6,%7}, {%8,%9}, {%0,%1,%2,%3};\n" \
                 : "+f"(d0), "+f"(d1), "+f"(d2), "+f"(d3) \
                 : "r"(a0), "r"(a1), "r"(a2), "r"(a3), "r"(b0), "r"(b1))

// ================= fp16 mma.sync GEMM, ldmatrix + SW128 (round 9, proven) =====
#define A_ST 16384
#define STG  32768
#define NST  3
#define GEMM_SMEM (NST * STG)

template<bool HALF_OUT>
__global__ __launch_bounds__(256, 2)
void gemm_h(int N, int K,
            const __half* __restrict__ A,
            const __half* __restrict__ Bt,
            void* __restrict__ Cout,
            const float* __restrict__ bias)
{
    extern __shared__ char smem[];
    const uint32_t sbase = smem_u32(smem);
    const int tid  = threadIdx.x;
    const int warp = tid >> 5;
    const int lane = tid & 31;
    const int g    = lane >> 2;
    const int t4   = lane & 3;
    const int wm0  = (warp & 1) * 64;
    const int wn0  = (warp >> 1) * 32;

    const size_t m0 = (size_t)blockIdx.y * 128;
    const size_t n0 = (size_t)blockIdx.x * 128;

    const int lrow = tid >> 3;
    const int lc8  = tid & 7;
    const __half* gA = A  + (m0 + lrow) * K + lc8 * 8;
    const __half* gB = Bt + (n0 + lrow) * K + lc8 * 8;
    const uint32_t stA = lrow * 128 + ((lc8 ^ (lrow & 7)) << 4);
    const uint32_t stB = stA + A_ST;

    uint32_t abase[4], bbase[2];
    {
        const uint32_t sw = (((lane >> 4) ^ (lane & 7)) << 4);
        #pragma unroll
        for (int mt = 0; mt < 4; mt++)
            abase[mt] = (wm0 + mt * 16 + (lane & 15)) * 128 + sw;
        #pragma unroll
        for (int p = 0; p < 2; p++)
            bbase[p] = A_ST + (wn0 + p * 16 + (lane & 15)) * 128 + sw;
    }

    const int nch = K >> 6;

    float acc[4][4][4];
    #pragma unroll
    for (int i = 0; i < 4; i++)
        #pragma unroll
        for (int j = 0; j < 4; j++)
            #pragma unroll
            for (int r = 0; r < 4; r++) acc[i][j][r] = 0.f;

    #pragma unroll
    for (int s = 0; s < 2; s++) {
        #pragma unroll
        for (int u = 0; u < 4; u++) {
            cp_async16(sbase + stA + s * STG + u * 4096, gA + (size_t)u * 32 * K + s * 64);
            cp_async16(sbase + stB + s * STG + u * 4096, gB + (size_t)u * 32 * K + s * 64);
        }
        asm volatile("cp.async.commit_group;\n");
    }

    for (int c = 0; c < nch; c++) {
        asm volatile("cp.async.wait_group 1;\n");
        __syncthreads();

        const int nc = c + 2;
        if (nc < nch) {
            const int ns = nc % 3;
            #pragma unroll
            for (int u = 0; u < 4; u++) {
                cp_async16(sbase + stA + ns * STG + u * 4096, gA + (size_t)u * 32 * K + nc * 64);
                cp_async16(sbase + stB + ns * STG + u * 4096, gB + (size_t)u * 32 * K + nc * 64);
            }
        }
        asm volatile("cp.async.commit_group;\n");

        const uint32_t so = sbase + (c % 3) * STG;

        #pragma unroll
        for (int ks = 0; ks < 4; ks++) {
            const uint32_t kx = (uint32_t)ks << 5;
            uint32_t a[4][4], b[4][2];
            #pragma unroll
            for (int mt = 0; mt < 4; mt++)
                LDSM4(a[mt][0], a[mt][1], a[mt][2], a[mt][3], so + (abase[mt] ^ kx));
            #pragma unroll
            for (int p = 0; p < 2; p++)
                LDSM4(b[2 * p][0], b[2 * p + 1][0], b[2 * p][1], b[2 * p + 1][1],
                      so + (bbase[p] ^ kx));
            #pragma unroll
            for (int mt = 0; mt < 4; mt++)
                #pragma unroll
                for (int nt = 0; nt < 4; nt++)
                    MMA16816(acc[mt][nt][0], acc[mt][nt][1], acc[mt][nt][2], acc[mt][nt][3],
                             a[mt][0], a[mt][1], a[mt][2], a[mt][3], b[nt][0], b[nt][1]);
        }
    }

    #pragma unroll
    for (int mt = 0; mt < 4; mt++) {
        const size_t r0 = m0 + wm0 + mt * 16 + g;
        const size_t r1 = r0 + 8;
        #pragma unroll
        for (int nt = 0; nt < 4; nt++) {
            const int col = (int)n0 + wn0 + nt * 8 + t4 * 2;
            if (HALF_OUT) {
                __half* C = (__half*)Cout;
                *(__half2*)(C + r0 * N + col) = __floats2half2_rn(acc[mt][nt][0], acc[mt][nt][1]);
                *(__half2*)(C + r1 * N + col) = __floats2half2_rn(acc[mt][nt][2], acc[mt][nt][3]);
            } else {
                float* C = (float*)Cout;
                float b0 = bias ? bias[col] : 0.f;
                float b1 = bias ? bias[col + 1] : 0.f;
                *(float2*)(C + r0 * N + col) = make_float2(acc[mt][nt][0] + b0, acc[mt][nt][1] + b1);
                *(float2*)(C + r1 * N + col) = make_float2(acc[mt][nt][2] + b0, acc[mt][nt][3] + b1);
            }
        }
    }
}

// ---------------- preprocessing: convert x (+rope table in block 0) ----------------
__global__ __launch_bounds__(256)
void convert_x_kernel(const float4* __restrict__ in, uint4* __restrict__ out, int n8,
                      const float* __restrict__ inv_freq, float2* __restrict__ rope) {
    if (blockIdx.x == 0) {
        for (int e = threadIdx.x; e < 1024; e += 256) {
            int t = e >> 5, j = e & 31;
            float sn, cs;
            sincosf((float)t * inv_freq[j], &sn, &cs);
            rope[e] = make_float2(cs, sn);
        }
    }
    int i = blockIdx.x * 256 + threadIdx.x;
    if (i >= n8) return;
    float4 f0 = in[2 * i], f1 = in[2 * i + 1];
    __half2 h[4];
    h[0] = __floats2half2_rn(f0.x, f0.y);
    h[1] = __floats2half2_rn(f0.z, f0.w);
    h[2] = __floats2half2_rn(f1.x, f1.y);
    h[3] = __floats2half2_rn(f1.z, f1.w);
    out[i] = *(const uint4*)h;
}

// transpose BOTH weights in one launch
__global__ __launch_bounds__(256)
void transpose_both_kernel(const float* __restrict__ Wq, const float* __restrict__ Wo,
                           __half* __restrict__ outq, __half* __restrict__ outo) {
    __shared__ float t[32][33];
    int bid = blockIdx.x;
    const float* in;
    __half* out;
    int Nn, n0, k0;
    const int Kk = 1024;
    if (bid < 3072) {
        in = Wq; out = outq; Nn = 3072;
        n0 = (bid % 96) * 32; k0 = (bid / 96) * 32;
    } else {
        bid -= 3072;
        in = Wo; out = outo; Nn = 1024;
        n0 = (bid % 32) * 32; k0 = (bid / 32) * 32;
    }
    const int tx = threadIdx.x & 31;
    const int ty = threadIdx.x >> 5;
    #pragma unroll
    for (int r = 0; r < 4; r++) {
        int kr = ty + r * 8;
        t[kr][tx] = in[(size_t)(k0 + kr) * Nn + n0 + tx];
    }
    __syncthreads();
    if (threadIdx.x < 64) {
        const int nl = threadIdx.x >> 1;
        const int kg = threadIdx.x & 1;
        __half h[16];
        #pragma unroll
        for (int o = 0; o < 16; o++)
            h[o] = __float2half_rn(t[kg * 16 + o][nl]);
        uint4* o4 = (uint4*)(out + (size_t)(n0 + nl) * Kk + k0 + kg * 16);
        o4[0] = ((const uint4*)h)[0];
        o4[1] = ((const uint4*)h)[1];
    }
}

// ---------------- fused attention: 4 CTAs/SM + vectorized P6 ----------------
#define TSEQ 32
#define DHD 64

struct __align__(16) AttnSmem {
    float qs[TSEQ][68];     // 8704 (pad 68: conflict-free P6 staging writes)
    float ks[TSEQ][68];     // 8704 (pad 68: conflict-free P4 k-frag loads)
    float vs[TSEQ][64];     // 8192 (reads broadcast/stride-1)
    float ms[DHD][64];      // 16384 (reads broadcast/stride-1)
    union {
        float skk[8][64];   // live P2..P3
        float sc[TSEQ][36]; // live P4..P6 (row stride 144B: 16B-aligned float4)
    } u;                    // 4608
    float sq[TSEQ][68];     // 8704 sigma(q) row-major
    float zs[DHD];          // 256
};                          // total 55552 B -> 4 CTAs/SM

__global__ __launch_bounds__(256, 4)
void attn_kernel(const __half* __restrict__ qkv,
                 const float* __restrict__ mem,
                 const float* __restrict__ zin,
                 const float* __restrict__ mem_beta,
                 const float2* __restrict__ rope_tab,
                 __half* __restrict__ out_mid,
                 float* __restrict__ new_mem,
                 float* __restrict__ new_z)
{
    extern __shared__ __align__(16) char smem_raw[];
    AttnSmem& S = *(AttnSmem*)smem_raw;

    const int bh   = blockIdx.x;
    const int s    = bh >> 4;
    const int head = bh & 15;
    const int b    = s / 576;
    const int rem  = s - b * 576;
    const int tid  = threadIdx.x;
    const int warp = tid >> 5;
    const int lane = tid & 31;
    const int row_base = b * 18432 + rem;
    const size_t mbase = (size_t)bh * (DHD * DHD);

    const float g = 1.f / (1.f + __expf(-mem_beta[head]));
    const float ig = 1.f - g;

    // ---- rope register prefetch (completes during P1/P2) ----
    float2 rp[4];
    #pragma unroll
    for (int k = 0; k < 4; k++) rp[k] = rope_tab[tid + k * 256];

    // ---- P1: load qkv (half2), mem, z ----
    for (int e = tid; e < 1024; e += 256) {
        int t = e >> 5, d2 = (e & 31) * 2;
        size_t base = (size_t)(row_base + t * 576) * 3072 + head * 64 + d2;
        float2 q = __half22float2(*(const __half2*)(qkv + base));
        float2 k = __half22float2(*(const __half2*)(qkv + base + 1024));
        float2 v = __half22float2(*(const __half2*)(qkv + base + 2048));
        S.qs[t][d2] = q.x; S.qs[t][d2 + 1] = q.y;
        S.ks[t][d2] = k.x; S.ks[t][d2 + 1] = k.y;
        S.vs[t][d2] = v.x; S.vs[t][d2 + 1] = v.y;
    }
    for (int e = tid; e < 4096; e += 256)
        ((float*)S.ms)[e] = mem[mbase + e];
    if (tid < DHD) S.zs[tid] = zin[(size_t)bh * DHD + tid];
    __syncthreads();

    // ---- P2: skk = sigma(sigma(k_raw[:8])) ; new_z ----
    for (int e = tid; e < 8 * DHD; e += 256) {
        int t = e >> 6, i = e & 63;
        S.u.skk[t][i] = sigma_fn(sigma_fn(S.ks[t][i]));
    }
    if (tid < DHD) {
        float acc = S.zs[tid];
        #pragma unroll
        for (int t = 0; t < TSEQ; t++) acc += sigma_fn(S.ks[t][tid]);
        new_z[(size_t)bh * DHD + tid] = acc;
    }
    __syncthreads();

    // ---- P3: new_mem + rotary (rope from registers) ----
    for (int e = tid; e < 4096; e += 256) {
        int i = e >> 6, j = e & 63;
        float acc = S.ms[i][j];
        #pragma unroll
        for (int t = 0; t < 8; t++) acc += S.u.skk[t][i] * S.vs[t][j];
        new_mem[mbase + e] = acc;
    }
    #pragma unroll
    for (int k = 0; k < 4; k++) {
        int e = tid + k * 256;
        int t = e >> 5, j = e & 31;
        float2 cssn = rp[k];
        float q0 = S.qs[t][2 * j], q1 = S.qs[t][2 * j + 1];
        S.qs[t][2 * j]     = q0 * cssn.x - q1 * cssn.y;
        S.qs[t][2 * j + 1] = q1 * cssn.x + q0 * cssn.y;
        float k0 = S.ks[t][2 * j], k1 = S.ks[t][2 * j + 1];
        S.ks[t][2 * j]     = k0 * cssn.x - k1 * cssn.y;
        S.ks[t][2 * j + 1] = k1 * cssn.x + k0 * cssn.y;
    }
    __syncthreads();

    // ---- P4: scores (2x2 reg tile) + sigma_q -> sq (row-major) ----
    {
        const int tr = tid >> 4;
        const int tc = tid & 15;
        float a00 = 0.f, a01 = 0.f, a10 = 0.f, a11 = 0.f;
        #pragma unroll
        for (int d = 0; d < DHD; d += 4) {
            float4 q0 = *(const float4*)&S.qs[tr][d];
            float4 q1 = *(const float4*)&S.qs[tr + 16][d];
            float4 k0 = *(const float4*)&S.ks[tc][d];
            float4 k1 = *(const float4*)&S.ks[tc + 16][d];
            a00 += q0.x * k0.x + q0.y * k0.y + q0.z * k0.z + q0.w * k0.w;
            a01 += q0.x * k1.x + q0.y * k1.y + q0.z * k1.z + q0.w * k1.w;
            a10 += q1.x * k0.x + q1.y * k0.y + q1.z * k0.z + q1.w * k0.w;
            a11 += q1.x * k1.x + q1.y * k1.y + q1.z * k1.z + q1.w * k1.w;
        }
        S.u.sc[tr][tc]           = a00 * 0.125f;
        S.u.sc[tr][tc + 16]      = a01 * 0.125f;
        S.u.sc[tr + 16][tc]      = a10 * 0.125f;
        S.u.sc[tr + 16][tc + 16] = a11 * 0.125f;
    }
    for (int e = tid; e < 2048; e += 256) {
        int t = e >> 6, dd = e & 63;
        S.sq[t][dd] = sigma_fn(S.qs[t][dd]);
    }
    __syncthreads();

    // ---- P5: warp-parallel softmax ----
    #pragma unroll
    for (int r = 0; r < 4; r++) {
        int t = warp * 4 + r;
        float v = (lane <= t) ? S.u.sc[t][lane] : -1e30f;
        float m = v;
        #pragma unroll
        for (int o = 16; o > 0; o >>= 1) m = fmaxf(m, __shfl_xor_sync(0xFFFFFFFFu, m, o));
        float ex = (lane <= t) ? __expf(v - m) : 0.f;
        float ssum = ex;
        #pragma unroll
        for (int o = 16; o > 0; o >>= 1) ssum += __shfl_xor_sync(0xFFFFFFFFu, ssum, o);
        S.u.sc[t][lane] = ex / ssum;
    }
    __syncthreads();

    // ---- P6: out = g*(sq@ms)/denom + (1-g)*(sc@vs), denom fused; stage to qs ----
    {
        const int dc = warp;
        const int t  = lane;
        const int dd0 = dc * 8;
        float4 aA0 = {0,0,0,0}, aA1 = {0,0,0,0};
        float4 aR0 = {0,0,0,0}, aR1 = {0,0,0,0};
        float ds = 0.f;

        #pragma unroll
        for (int tt4 = 0; tt4 < 8; tt4++) {
            float4 sv4 = *(const float4*)&S.u.sc[t][tt4 * 4];
            float svs[4] = {sv4.x, sv4.y, sv4.z, sv4.w};
            #pragma unroll
            for (int e2 = 0; e2 < 4; e2++) {
                int tt = tt4 * 4 + e2;
                float4 v0 = *(const float4*)&S.vs[tt][dd0];
                float4 v1 = *(const float4*)&S.vs[tt][dd0 + 4];
                aA0.x += svs[e2] * v0.x; aA0.y += svs[e2] * v0.y;
                aA0.z += svs[e2] * v0.z; aA0.w += svs[e2] * v0.w;
                aA1.x += svs[e2] * v1.x; aA1.y += svs[e2] * v1.y;
                aA1.z += svs[e2] * v1.z; aA1.w += svs[e2] * v1.w;
            }
        }
        #pragma unroll
        for (int kx4 = 0; kx4 < 16; kx4++) {
            float4 sq4 = *(const float4*)&S.sq[t][kx4 * 4];
            float4 z4  = *(const float4*)&S.zs[kx4 * 4];
            ds += sq4.x * z4.x + sq4.y * z4.y + sq4.z * z4.z + sq4.w * z4.w;
            float sqs[4] = {sq4.x, sq4.y, sq4.z, sq4.w};
            #pragma unroll
            for (int e2 = 0; e2 < 4; e2++) {
                int kx = kx4 * 4 + e2;
                float4 m0 = *(const float4*)&S.ms[kx][dd0];
                float4 m1 = *(const float4*)&S.ms[kx][dd0 + 4];
                aR0.x += sqs[e2] * m0.x; aR0.y += sqs[e2] * m0.y;
                aR0.z += sqs[e2] * m0.z; aR0.w += sqs[e2] * m0.w;
                aR1.x += sqs[e2] * m1.x; aR1.y += sqs[e2] * m1.y;
                aR1.z += sqs[e2] * m1.z; aR1.w += sqs[e2] * m1.w;
            }
        }
        const float gi = g / ds;
        float4 o0, o1;
        o0.x = gi * aR0.x + ig * aA0.x;  o0.y = gi * aR0.y + ig * aA0.y;
        o0.z = gi * aR0.z + ig * aA0.z;  o0.w = gi * aR0.w + ig * aA0.w;
        o1.x = gi * aR1.x + ig * aA1.x;  o1.y = gi * aR1.y + ig * aA1.y;
        o1.z = gi * aR1.z + ig * aA1.z;  o1.w = gi * aR1.w + ig * aA1.w;
        *(float4*)&S.qs[t][dd0]     = o0;
        *(float4*)&S.qs[t][dd0 + 4] = o1;
    }
    __syncthreads();

    // ---- P7: coalesced fp16 writeback ----
    for (int e = tid; e < 1024; e += 256) {
        int t = e >> 5, dd = (e & 31) * 2;
        __half2 h = __floats2half2_rn(S.qs[t][dd], S.qs[t][dd + 1]);
        *(__half2*)(out_mid + (size_t)(row_base + t * 576) * 1024 + head * 64 + dd) = h;
    }
}

// ---------------- launch ----------------
extern "C" void kernel_launch(void* const* d_in, const int* in_sizes, int n_in,
                              void* d_out, int out_size) {
    const float* x        = (const float*)d_in[0];
    const float* mem      = (const float*)d_in[1];
    const float* z        = (const float*)d_in[2];
    const float* W_qkv    = (const float*)d_in[3];
    const float* W_out    = (const float*)d_in[4];
    const float* b_out    = (const float*)d_in[5];
    const float* mem_beta = (const float*)d_in[6];
    const float* inv_freq = (const float*)d_in[7];

    float* x_out = (float*)d_out;
    float* nmem  = x_out + 37748736UL;
    float* nz    = x_out + 113246208UL;

    __half *qkv = nullptr, *mid = nullptr, *xh = nullptr, *wt = nullptr;
    float2* rope = nullptr;
    cudaGetSymbolAddress((void**)&qkv, g_qkv_h);
    cudaGetSymbolAddress((void**)&mid, g_mid_h);
    cudaGetSymbolAddress((void**)&xh, g_x_h);
    cudaGetSymbolAddress((void**)&wt, g_wt_h);
    cudaGetSymbolAddress((void**)&rope, g_rope);
    __half* wt_qkv = wt;
    __half* wt_out = wt + 3145728UL;

    cudaFuncSetAttribute(gemm_h<true>, cudaFuncAttributeMaxDynamicSharedMemorySize, GEMM_SMEM);
    cudaFuncSetAttribute(gemm_h<false>, cudaFuncAttributeMaxDynamicSharedMemorySize, GEMM_SMEM);
    cudaFuncSetAttribute(attn_kernel, cudaFuncAttributeMaxDynamicSharedMemorySize,
                         (int)sizeof(AttnSmem));

    const int M = 36864, K = 1024;

    convert_x_kernel<<<(M * K / 8 + 255) / 256, 256>>>(
        (const float4*)x, (uint4*)xh, M * K / 8, inv_freq, rope);
    transpose_both_kernel<<<4096, 256>>>(W_qkv, W_out, wt_qkv, wt_out);
    gemm_h<true><<<dim3(3072 / 128, M / 128), 256, GEMM_SMEM>>>(
        3072, K, xh, wt_qkv, qkv, nullptr);
    attn_kernel<<<18432, 256, sizeof(AttnSmem)>>>(
        qkv, mem, z, mem_beta, rope, mid, nmem, nz);
    gemm_h<false><<<dim3(1024 / 128, M / 128), 256, GEMM_SMEM>>>(
        1024, K, mid, wt_out, x_out, b_out);
}